// round 3
// baseline (speedup 1.0000x reference)
#include <cuda_runtime.h>

// Problem constants
#define NBL 32   // B*L
#define NC  32   // channels (in == out)
#define NH  128
#define NW  256
#define NJ  32   // kept W-modes
#define NP  64   // kept H-rows: {0..31, 96..127}

typedef unsigned long long u64;

// ---- packed fp32x2 helpers (FFMA2 is PTX-only; ptxas never auto-fuses) ----
__device__ __forceinline__ u64 dup2(float v) {
    u64 r; asm("mov.b64 %0,{%1,%1};" : "=l"(r) : "f"(v)); return r;
}
__device__ __forceinline__ void fma2(u64 &d, u64 a, u64 b) {
    asm("fma.rn.f32x2 %0,%1,%2,%0;" : "+l"(d) : "l"(a), "l"(b));
}
__device__ __forceinline__ float2 up2(u64 v) {
    float2 f; asm("mov.b64 {%0,%1},%2;" : "=f"(f.x), "=f"(f.y) : "l"(v)); return f;
}

// ---------------- scratch (__device__ globals; no allocations) ----------------
// Z / Kf / G layout: [batch][p][comp][j]  (comp: 0=re, 1=im; j contiguous)
__device__ __align__(16) float g_Z [(size_t)NBL*NC*NP*2*NJ];   // x_f modes (16.8MB)
__device__ __align__(16) float g_Kf[(size_t)NC*NP*2*NJ];       // k_f modes
__device__ __align__(16) float g_G [(size_t)NBL*NC*NP*2*NJ];   // mixed modes (16.8MB)
__device__ __align__(16) float g_DW[NW*64];                    // fwd W-DFT  [w][comp*32+j]
__device__ __align__(16) float g_CH[NH*NP];                    // fwd H cos  [h][p]
__device__ __align__(16) float g_SH[NH*NP];                    // fwd H sin  [h][p]
__device__ __align__(16) float g_CI[NP*NH];                    // inv H cos/H [p][h]
__device__ __align__(16) float g_SI[NP*NH];                    // inv H sin/H [p][h]
__device__ __align__(16) float g_DI[64*NW];                    // inv W c2r  [comp*32+j][w]
__device__ __align__(16) float g_Wmix[(size_t)NP*NJ*NC*NC*2];  // [mode][c][o][2] (16.8MB)

__device__ __forceinline__ int row_of_p(int p) { return (p < 32) ? p : (64 + p); }

// ---------------- twiddle init ----------------
__global__ void init_twiddles() {
    int idx = blockIdx.x * blockDim.x + threadIdx.x;  // >= 16384 threads
    // g_DW[w][r]: r = comp*32+j; comp0: cos(2pi jw/W), comp1: -sin(2pi jw/W)
    if (idx < NW * 64) {
        int w = idx >> 6, r = idx & 63, comp = r >> 5, j = r & 31;
        int t = (j * w) % NW;
        float s, c; sincospif(2.0f * (float)t / (float)NW, &s, &c);
        g_DW[idx] = comp ? -s : c;
    }
    if (idx < NH * NP) {
        {
            int h = idx / NP, p = idx % NP;
            int t = (row_of_p(p) * h) % NH;
            float s, c; sincospif(2.0f * (float)t / (float)NH, &s, &c);
            g_CH[idx] = c; g_SH[idx] = s;
        }
        {
            int p = idx / NH, h = idx % NH;
            int t = (row_of_p(p) * h) % NH;
            float s, c; sincospif(2.0f * (float)t / (float)NH, &s, &c);
            g_CI[idx] = c * (1.0f / (float)NH);
            g_SI[idx] = s * (1.0f / (float)NH);
        }
    }
    // g_DI[r][w]: comp0: (j==0?1:2)/W*cos ; comp1: j==0?0 : -(2/W)*sin
    if (idx < 64 * NW) {
        int r = idx >> 8, w = idx & 255, comp = r >> 5, j = r & 31;
        int t = (j * w) % NW;
        float s, c; sincospif(2.0f * (float)t / (float)NW, &s, &c);
        float v;
        if (comp == 0) v = ((j == 0) ? 1.0f : 2.0f) * (1.0f / (float)NW) * c;
        else           v = (j == 0) ? 0.0f : (-2.0f / (float)NW) * s;
        g_DI[idx] = v;
    }
}

// ---------------- weight transpose: [c][o][i][j] -> [mode][c][o][2] ----------------
__global__ void prep_w(const float* __restrict__ w1r, const float* __restrict__ w1i,
                       const float* __restrict__ w2r, const float* __restrict__ w2i) {
    int idx = blockIdx.x * blockDim.x + threadIdx.x;
    if (idx >= NP * NJ * NC * NC) return;
    int o = idx % NC;
    int c = (idx / NC) % NC;
    int j = (idx / (NC * NC)) % NJ;
    int p = idx / (NC * NC * NJ);
    int i = (p < 32) ? p : (p - 32);
    const float* wr = (p < 32) ? w1r : w2r;
    const float* wi = (p < 32) ? w1i : w2i;
    int widx = ((c * NC + o) * 32 + i) * 32 + j;
    g_Wmix[(size_t)idx * 2 + 0] = wr[widx];
    g_Wmix[(size_t)idx * 2 + 1] = wi[widx];
}

// ---------------- fused forward: per (batch) block: W-DFT GEMM then H-DFT ----------------
// in:  X[batch][h=128][w=256] real.  out: Z[batch][p=64][comp=2][j=32]
__global__ __launch_bounds__(256, 2) void fwd_fused(const float* __restrict__ X,
                                                    float* __restrict__ Zout) {
    __shared__ float As[128][17];   // x chunk  [h][wsub]  (pad 17: conflict-free scalar reads)
    __shared__ float Bs[16][64];    // DW chunk [wsub][r]
    __shared__ float Ts[128][66];   // T = x @ DW  [h][r]  (stride 66: 8B-aligned pairs)
    int batch = blockIdx.x;
    int t  = threadIdx.x;
    int tx = t & 7, ty = t >> 3;    // pairs over r, rows over h
    int h0 = ty * 4;

    u64 acc[4][4];
#pragma unroll
    for (int i = 0; i < 4; i++)
#pragma unroll
        for (int m = 0; m < 4; m++) acc[i][m] = 0ull;

    const float* xb = X + (size_t)batch * NH * NW;
    int lr = t >> 1, lw = (t & 1) * 8;
    for (int k0 = 0; k0 < NW; k0 += 16) {
        float4 v0 = *(const float4*)(xb + (size_t)lr * NW + k0 + lw);
        float4 v1 = *(const float4*)(xb + (size_t)lr * NW + k0 + lw + 4);
        As[lr][lw + 0] = v0.x; As[lr][lw + 1] = v0.y; As[lr][lw + 2] = v0.z; As[lr][lw + 3] = v0.w;
        As[lr][lw + 4] = v1.x; As[lr][lw + 5] = v1.y; As[lr][lw + 6] = v1.z; As[lr][lw + 7] = v1.w;
        {
            int br = t >> 4, bc = (t & 15) * 4;
            *(float4*)&Bs[br][bc] = *(const float4*)(g_DW + (size_t)(k0 + br) * 64 + bc);
        }
        __syncthreads();
#pragma unroll
        for (int kk = 0; kk < 16; kk++) {
            u64 b0 = *(const u64*)&Bs[kk][tx * 2];
            u64 b1 = *(const u64*)&Bs[kk][tx * 2 + 16];
            u64 b2 = *(const u64*)&Bs[kk][tx * 2 + 32];
            u64 b3 = *(const u64*)&Bs[kk][tx * 2 + 48];
#pragma unroll
            for (int i = 0; i < 4; i++) {
                u64 a = dup2(As[h0 + i][kk]);
                fma2(acc[i][0], a, b0);
                fma2(acc[i][1], a, b1);
                fma2(acc[i][2], a, b2);
                fma2(acc[i][3], a, b3);
            }
        }
        __syncthreads();
    }
#pragma unroll
    for (int i = 0; i < 4; i++)
#pragma unroll
        for (int m = 0; m < 4; m++)
            *(float2*)&Ts[h0 + i][tx * 2 + m * 16] = up2(acc[i][m]);
    __syncthreads();

    // stage 2: H-DFT.  Zr = sum_h ch*Tr + sh*Ti ;  Zi = sum_h ch*Ti - sh*Tr
    int p = t & 63, q = t >> 6;
    int comp = q >> 1, jh = q & 1, j0 = jh * 16;
    int ofsA = comp ? 32 : 0, ofsB = 32 - ofsA;
    u64 z[8];
#pragma unroll
    for (int m = 0; m < 8; m++) z[m] = 0ull;
    for (int h = 0; h < NH; h++) {
        float ch = g_CH[h * NP + p];
        float sh = g_SH[h * NP + p];
        u64 cd = dup2(ch);
        u64 sd = dup2(comp ? -sh : sh);
#pragma unroll
        for (int m = 0; m < 8; m++) {
            u64 A = *(const u64*)&Ts[h][ofsA + j0 + 2 * m];
            u64 B = *(const u64*)&Ts[h][ofsB + j0 + 2 * m];
            fma2(z[m], cd, A);
            fma2(z[m], sd, B);
        }
    }
    float* dst = Zout + ((((size_t)batch * NP + p) * 2 + comp) * NJ + j0);
#pragma unroll
    for (int m = 0; m < 8; m++) *(float2*)&dst[2 * m] = up2(z[m]);
}

// ---------------- per-mode channel mix: G[bl,o] = sum_c (Z[bl,c]*Kf[c]) * W[c,o] ----------------
__global__ __launch_bounds__(1024) void mix_modes() {
    int mode = blockIdx.x;          // p*32 + j
    int p = mode >> 5, j = mode & 31;
    __shared__ float2 zk[NC][NBL];
    __shared__ float2 ws[NC][NC];
    int t = threadIdx.x;
    {
        int c1 = t >> 5, lo = t & 31;   // lo = bl for zk, = o for ws
        int blc = lo * NC + c1;
        size_t zb = (((size_t)blc * NP + p) * 2) * NJ + j;
        float zr = g_Z[zb], zi = g_Z[zb + NJ];
        size_t kb = (((size_t)c1 * NP + p) * 2) * NJ + j;
        float kr = g_Kf[kb], ki = g_Kf[kb + NJ];
        zk[c1][lo] = make_float2(zr * kr - zi * ki, zr * ki + zi * kr);
        ws[c1][lo] = ((const float2*)(g_Wmix + (size_t)mode * NC * NC * 2))[t];
    }
    __syncthreads();
    int o = t & 31, bl = t >> 5;
    float ar = 0.0f, ai = 0.0f;
#pragma unroll
    for (int c = 0; c < NC; c++) {
        float2 w = ws[c][o];
        float2 x = zk[c][bl];
        ar += w.x * x.x - w.y * x.y;
        ai += w.x * x.y + w.y * x.x;
    }
    size_t gb = (((size_t)(bl * NC + o) * NP + p) * 2) * NJ + j;
    g_G[gb] = ar; g_G[gb + NJ] = ai;
}

// ---------------- fused inverse: per (blo) block: inverse-H then inverse-W c2r ----------------
// G[blo][p][comp][j] -> tmpT[r=comp*32+j][h] -> out[blo][h][w]
__global__ __launch_bounds__(512, 1) void inv_fused(float* __restrict__ out) {
    extern __shared__ float sm[];
    float* DIs = sm;                 // [64][256]  64KB
    float* Tm  = sm + 64 * 256;      // [64][132]  33.8KB (pad 4: aligned float4 rows)
    float* Gs  = Tm + 64 * 132;      // [64][64]   16KB
    int blo = blockIdx.x;
    int t = threadIdx.x;

    for (int i = t; i < 64 * 256 / 4; i += 512)
        ((float4*)DIs)[i] = ((const float4*)g_DI)[i];
    {
        const float4* src = (const float4*)(g_G + (size_t)blo * NP * 2 * NJ);
        for (int i = t; i < 64 * 64 / 4; i += 512) ((float4*)Gs)[i] = src[i];
    }
    __syncthreads();

    // stage A: inverse H.  Tr = sum_p ci*Gr - si*Gi ;  Ti = sum_p ci*Gi + si*Gr
    {
        int h = t & 127, q = t >> 7;
        int comp = q >> 1, jh = q & 1, j0 = jh * 16;
        int ofsA = comp ? 32 : 0, ofsB = 32 - ofsA;
        u64 z[8];
#pragma unroll
        for (int m = 0; m < 8; m++) z[m] = 0ull;
        for (int p = 0; p < NP; p++) {
            float ci = g_CI[p * NH + h];
            float si = g_SI[p * NH + h];
            u64 cd = dup2(ci);
            u64 sd = dup2(comp ? si : -si);
            const float* gr = Gs + p * 64;
#pragma unroll
            for (int m = 0; m < 8; m++) {
                u64 A = *(const u64*)&gr[ofsA + j0 + 2 * m];
                u64 B = *(const u64*)&gr[ofsB + j0 + 2 * m];
                fma2(z[m], cd, A);
                fma2(z[m], sd, B);
            }
        }
#pragma unroll
        for (int m = 0; m < 8; m++) {
            float2 v = up2(z[m]);
            Tm[(comp * 32 + j0 + 2 * m) * 132 + h]     = v.x;
            Tm[(comp * 32 + j0 + 2 * m + 1) * 132 + h] = v.y;
        }
    }
    __syncthreads();

    // stage B: out[h][w] = sum_r Tm[r][h] * DIs[r][w]
    int tx = t & 15, ty = t >> 4;
    int h0 = ty * 4;
    float* ob = out + (size_t)blo * NH * NW;
    for (int chk = 0; chk < 2; chk++) {
        int wbase = chk * 128;
        u64 acc[4][4];
#pragma unroll
        for (int i = 0; i < 4; i++)
#pragma unroll
            for (int m = 0; m < 4; m++) acc[i][m] = 0ull;
#pragma unroll 8
        for (int k = 0; k < 64; k++) {
            const float* dr = DIs + k * 256 + wbase;
            u64 b0 = *(const u64*)&dr[tx * 2];
            u64 b1 = *(const u64*)&dr[tx * 2 + 32];
            u64 b2 = *(const u64*)&dr[tx * 2 + 64];
            u64 b3 = *(const u64*)&dr[tx * 2 + 96];
            const float* tr = Tm + k * 132 + h0;
#pragma unroll
            for (int i = 0; i < 4; i++) {
                u64 a = dup2(tr[i]);
                fma2(acc[i][0], a, b0);
                fma2(acc[i][1], a, b1);
                fma2(acc[i][2], a, b2);
                fma2(acc[i][3], a, b3);
            }
        }
#pragma unroll
        for (int i = 0; i < 4; i++)
#pragma unroll
            for (int m = 0; m < 4; m++)
                *(float2*)&ob[(size_t)(h0 + i) * NW + wbase + m * 32 + tx * 2] = up2(acc[i][m]);
    }
}

// ---------------- host launcher ----------------
extern "C" void kernel_launch(void* const* d_in, const int* in_sizes, int n_in,
                              void* d_out, int out_size) {
    const float* x   = (const float*)d_in[0];
    const float* k   = (const float*)d_in[1];
    const float* w1r = (const float*)d_in[2];
    const float* w1i = (const float*)d_in[3];
    const float* w2r = (const float*)d_in[4];
    const float* w2i = (const float*)d_in[5];
    float* out = (float*)d_out;
    (void)in_sizes; (void)n_in; (void)out_size;

    void *pZ, *pKf;
    cudaGetSymbolAddress(&pZ,  g_Z);
    cudaGetSymbolAddress(&pKf, g_Kf);

    const int INV_SMEM = (64 * 256 + 64 * 132 + 64 * 64) * 4;  // 115712 B
    cudaFuncSetAttribute(inv_fused, cudaFuncAttributeMaxDynamicSharedMemorySize, INV_SMEM);

    init_twiddles<<<64, 256>>>();
    prep_w<<<8192, 256>>>(w1r, w1i, w2r, w2i);

    // fused forward W-DFT + H-DFT (k first: tiny, fills Kf)
    fwd_fused<<<NC, 256>>>(k, (float*)pKf);
    fwd_fused<<<NBL * NC, 256>>>(x, (float*)pZ);

    // per-mode: conv (x_f * k_f) + channel mixing
    mix_modes<<<NP * NJ, 1024>>>();

    // fused inverse H + inverse W (c2r) straight into output
    inv_fused<<<NBL * NC, 512, INV_SMEM>>>(out);
}

// round 4
// speedup vs baseline: 1.1268x; 1.1268x over previous
#include <cuda_runtime.h>

// Problem constants
#define NBL 32   // B*L
#define NC  32   // channels
#define NH  128
#define NW  256
#define NJ  32   // kept W-modes
#define NP  64   // kept H-rows: {0..31, 96..127}

typedef unsigned long long u64;

// ---- packed fp32x2 helpers (FFMA2 is PTX-only) ----
__device__ __forceinline__ u64 dup2(float v) {
    u64 r; asm("mov.b64 %0,{%1,%1};" : "=l"(r) : "f"(v)); return r;
}
__device__ __forceinline__ void fma2(u64 &d, u64 a, u64 b) {
    asm("fma.rn.f32x2 %0,%1,%2,%0;" : "+l"(d) : "l"(a), "l"(b));
}
__device__ __forceinline__ float2 up2(u64 v) {
    float2 f; asm("mov.b64 {%0,%1},%2;" : "=f"(f.x), "=f"(f.y) : "l"(v)); return f;
}

// ---------------- scratch ----------------
// T / tmp layout: [m = batch*128+h][r = comp*32+j]
// Z / Kf / G layout: [batch][p][comp][j]
__device__ __align__(16) float g_T  [(size_t)NBL*NC*NH*64];
__device__ __align__(16) float g_Tk [(size_t)NC*NH*64];
__device__ __align__(16) float g_Z  [(size_t)NBL*NC*NP*2*NJ];
__device__ __align__(16) float g_Kf [(size_t)NC*NP*2*NJ];
__device__ __align__(16) float g_G  [(size_t)NBL*NC*NP*2*NJ];
__device__ __align__(16) float g_tmp[(size_t)NBL*NC*NH*64];
__device__ __align__(16) float g_DW [NW*64];     // fwd W-DFT  [w][r]
__device__ __align__(16) float g_CH [NH*NP];     // fwd H cos  [h][p]
__device__ __align__(16) float g_SH [NH*NP];     // fwd H sin  [h][p]
__device__ __align__(16) float g_CI [NP*NH];     // inv H cos/H [p][h]
__device__ __align__(16) float g_SI [NP*NH];     // inv H sin/H [p][h]
__device__ __align__(16) float g_DI [64*NW];     // inv W c2r  [r][w]
__device__ __align__(16) float g_Wmix[(size_t)NP*NJ*NC*NC*2];

__device__ __forceinline__ int row_of_p(int p) { return (p < 32) ? p : (64 + p); }

// ---------------- twiddle init ----------------
__global__ void init_twiddles() {
    int idx = blockIdx.x * blockDim.x + threadIdx.x;  // 16384 threads
    if (idx < NW * 64) {
        int w = idx >> 6, r = idx & 63, comp = r >> 5, j = r & 31;
        int t = (j * w) % NW;
        float s, c; sincospif(2.0f * (float)t / (float)NW, &s, &c);
        g_DW[idx] = comp ? -s : c;
    }
    if (idx < NH * NP) {
        {
            int h = idx / NP, p = idx % NP;
            int t = (row_of_p(p) * h) % NH;
            float s, c; sincospif(2.0f * (float)t / (float)NH, &s, &c);
            g_CH[idx] = c; g_SH[idx] = s;
        }
        {
            int p = idx / NH, h = idx % NH;
            int t = (row_of_p(p) * h) % NH;
            float s, c; sincospif(2.0f * (float)t / (float)NH, &s, &c);
            g_CI[idx] = c * (1.0f / (float)NH);
            g_SI[idx] = s * (1.0f / (float)NH);
        }
    }
    if (idx < 64 * NW) {
        int r = idx >> 8, w = idx & 255, comp = r >> 5, j = r & 31;
        int t = (j * w) % NW;
        float s, c; sincospif(2.0f * (float)t / (float)NW, &s, &c);
        float v;
        if (comp == 0) v = ((j == 0) ? 1.0f : 2.0f) * (1.0f / (float)NW) * c;
        else           v = (j == 0) ? 0.0f : (-2.0f / (float)NW) * s;
        g_DI[idx] = v;
    }
}

// ---------------- weight transpose: [c][o][i][j] -> [mode][c][o][2] ----------------
__global__ void prep_w(const float* __restrict__ w1r, const float* __restrict__ w1i,
                       const float* __restrict__ w2r, const float* __restrict__ w2i) {
    int idx = blockIdx.x * blockDim.x + threadIdx.x;
    if (idx >= NP * NJ * NC * NC) return;
    int o = idx % NC;
    int c = (idx / NC) % NC;
    int j = (idx / (NC * NC)) % NJ;
    int p = idx / (NC * NC * NJ);
    int i = (p < 32) ? p : (p - 32);
    const float* wr = (p < 32) ? w1r : w2r;
    const float* wi = (p < 32) ? w1i : w2i;
    int widx = ((c * NC + o) * 32 + i) * 32 + j;
    g_Wmix[(size_t)idx * 2 + 0] = wr[widx];
    g_Wmix[(size_t)idx * 2 + 1] = wi[widx];
}

// ---------------- FFMA2 GEMM: C[M,NDIM] = A[M,KDIM] * B[KDIM,NDIM] ----------------
// 128 threads, BM=128, BN=64, BK=32, 8x8 per-thread tile paired over n.
// A staged transposed + duplicated: As2[k][m] = {a,a}; B staged natural.
template<int KDIM, int NDIM>
__global__ __launch_bounds__(128, 4) void gemm2(const float* __restrict__ A,
                                                const float* __restrict__ Bm,
                                                float* __restrict__ Cm) {
    __shared__ float2 As2[32][129];
    __shared__ float  Bs[32][68];
    int m0 = blockIdx.y * 128, n0 = blockIdx.x * 64;
    int t = threadIdx.x;
    int tx = t & 7, ty = t >> 3;   // tx: n-octant, ty: 0..15

    u64 acc[8][4];
#pragma unroll
    for (int i = 0; i < 8; i++)
#pragma unroll
        for (int m = 0; m < 4; m++) acc[i][m] = 0ull;

    for (int k0 = 0; k0 < KDIM; k0 += 32) {
        // stage A (transpose + dup): rows ty+16*rr, k chunk tx*4
#pragma unroll
        for (int rr = 0; rr < 8; rr++) {
            int row = ty + 16 * rr;
            float4 v = *(const float4*)(A + (size_t)(m0 + row) * KDIM + k0 + tx * 4);
            As2[tx * 4 + 0][row] = make_float2(v.x, v.x);
            As2[tx * 4 + 1][row] = make_float2(v.y, v.y);
            As2[tx * 4 + 2][row] = make_float2(v.z, v.z);
            As2[tx * 4 + 3][row] = make_float2(v.w, v.w);
        }
        // stage B
#pragma unroll
        for (int i = 0; i < 4; i++) {
            int f = t + 128 * i;           // 512 float4 over [32][64]
            int r = f >> 4, c = (f & 15) * 4;
            *(float4*)&Bs[r][c] = *(const float4*)(Bm + (size_t)(k0 + r) * NDIM + n0 + c);
        }
        __syncthreads();
#pragma unroll 8
        for (int kk = 0; kk < 32; kk++) {
            u64 b0 = *(const u64*)&Bs[kk][tx * 2];
            u64 b1 = *(const u64*)&Bs[kk][tx * 2 + 16];
            u64 b2 = *(const u64*)&Bs[kk][tx * 2 + 32];
            u64 b3 = *(const u64*)&Bs[kk][tx * 2 + 48];
#pragma unroll
            for (int i = 0; i < 8; i++) {
                u64 a = *(const u64*)&As2[kk][ty * 8 + i];
                fma2(acc[i][0], a, b0);
                fma2(acc[i][1], a, b1);
                fma2(acc[i][2], a, b2);
                fma2(acc[i][3], a, b3);
            }
        }
        __syncthreads();
    }
#pragma unroll
    for (int i = 0; i < 8; i++)
#pragma unroll
        for (int m = 0; m < 4; m++)
            *(float2*)&Cm[(size_t)(m0 + ty * 8 + i) * NDIM + n0 + tx * 2 + 16 * m] = up2(acc[i][m]);
}

// ---------------- forward H-DFT: T[batch][h][r] -> Z[batch][p][comp][j] ----------------
__global__ __launch_bounds__(256) void fwdH(const float* __restrict__ Tin,
                                            float* __restrict__ Zout) {
    __shared__ float Ts[128][68];
    int batch = blockIdx.x, t = threadIdx.x;
    const float* src = Tin + (size_t)batch * NH * 64;
#pragma unroll
    for (int q = 0; q < 8; q++) {
        int f = t + 256 * q;               // 2048 float4 over [128][64]
        int r = f >> 4, c = (f & 15) * 4;
        *(float4*)&Ts[r][c] = *(const float4*)(src + (size_t)f * 4);
    }
    __syncthreads();

    int p = t & 63, jg = t >> 6, j0 = jg * 8;
    u64 zr[4] = {0, 0, 0, 0}, zi[4] = {0, 0, 0, 0};
#pragma unroll 4
    for (int h = 0; h < NH; h++) {
        float ch = g_CH[h * NP + p];
        float sh = g_SH[h * NP + p];
        u64 cd = dup2(ch), sd = dup2(sh), nd = dup2(-sh);
#pragma unroll
        for (int m = 0; m < 4; m++) {
            u64 tr = *(const u64*)&Ts[h][j0 + 2 * m];
            u64 ti = *(const u64*)&Ts[h][32 + j0 + 2 * m];
            fma2(zr[m], cd, tr); fma2(zr[m], sd, ti);
            fma2(zi[m], cd, ti); fma2(zi[m], nd, tr);
        }
    }
    float* dr = Zout + (((size_t)batch * NP + p) * 2 + 0) * NJ + j0;
    float* di = Zout + (((size_t)batch * NP + p) * 2 + 1) * NJ + j0;
#pragma unroll
    for (int m = 0; m < 4; m++) {
        *(float2*)&dr[2 * m] = up2(zr[m]);
        *(float2*)&di[2 * m] = up2(zi[m]);
    }
}

// ---------------- per-mode channel mix ----------------
__global__ __launch_bounds__(1024) void mix_modes() {
    int mode = blockIdx.x;          // p*32 + j
    int p = mode >> 5, j = mode & 31;
    __shared__ float2 zk[NC][NBL];
    __shared__ float2 ws[NC][NC];
    int t = threadIdx.x;
    {
        int c1 = t >> 5, lo = t & 31;
        int blc = lo * NC + c1;
        size_t zb = (((size_t)blc * NP + p) * 2) * NJ + j;
        float zr = g_Z[zb], zi = g_Z[zb + NJ];
        size_t kb = (((size_t)c1 * NP + p) * 2) * NJ + j;
        float kr = g_Kf[kb], ki = g_Kf[kb + NJ];
        zk[c1][lo] = make_float2(zr * kr - zi * ki, zr * ki + zi * kr);
        ws[c1][lo] = ((const float2*)(g_Wmix + (size_t)mode * NC * NC * 2))[t];
    }
    __syncthreads();
    int o = t & 31, bl = t >> 5;
    float ar = 0.0f, ai = 0.0f;
#pragma unroll
    for (int c = 0; c < NC; c++) {
        float2 w = ws[c][o];
        float2 x = zk[c][bl];
        ar += w.x * x.x - w.y * x.y;
        ai += w.x * x.y + w.y * x.x;
    }
    size_t gb = (((size_t)(bl * NC + o) * NP + p) * 2) * NJ + j;
    g_G[gb] = ar; g_G[gb + NJ] = ai;
}

// ---------------- inverse H-DFT: G[blo][p][comp][j] -> tmp[blo*128+h][r] ----------------
__global__ __launch_bounds__(256) void invH() {
    __shared__ float Gs[64][68];
    int blo = blockIdx.x, t = threadIdx.x;
    const float* src = g_G + (size_t)blo * NP * 64;
#pragma unroll
    for (int q = 0; q < 4; q++) {
        int f = t + 256 * q;               // 1024 float4 over [64][64]
        int r = f >> 4, c = (f & 15) * 4;
        *(float4*)&Gs[r][c] = *(const float4*)(src + (size_t)f * 4);
    }
    __syncthreads();

    int h = t & 127, q = t >> 7, j0 = q * 16;
    u64 tr[8], ti[8];
#pragma unroll
    for (int m = 0; m < 8; m++) { tr[m] = 0ull; ti[m] = 0ull; }
#pragma unroll 2
    for (int p = 0; p < NP; p++) {
        float ci = g_CI[p * NH + h];
        float si = g_SI[p * NH + h];
        u64 cd = dup2(ci), sd = dup2(si), nd = dup2(-si);
#pragma unroll
        for (int m = 0; m < 8; m++) {
            u64 gr = *(const u64*)&Gs[p][j0 + 2 * m];
            u64 gi = *(const u64*)&Gs[p][32 + j0 + 2 * m];
            fma2(tr[m], cd, gr); fma2(tr[m], nd, gi);
            fma2(ti[m], cd, gi); fma2(ti[m], sd, gr);
        }
    }
    float* dst = g_tmp + ((size_t)blo * NH + h) * 64;
#pragma unroll
    for (int m = 0; m < 8; m++) {
        *(float2*)&dst[j0 + 2 * m]      = up2(tr[m]);
        *(float2*)&dst[32 + j0 + 2 * m] = up2(ti[m]);
    }
}

// ---------------- host launcher ----------------
extern "C" void kernel_launch(void* const* d_in, const int* in_sizes, int n_in,
                              void* d_out, int out_size) {
    const float* x   = (const float*)d_in[0];
    const float* k   = (const float*)d_in[1];
    const float* w1r = (const float*)d_in[2];
    const float* w1i = (const float*)d_in[3];
    const float* w2r = (const float*)d_in[4];
    const float* w2i = (const float*)d_in[5];
    float* out = (float*)d_out;
    (void)in_sizes; (void)n_in; (void)out_size;

    void *pT, *pTk, *pZ, *pKf, *pTmp, *pDW, *pDI;
    cudaGetSymbolAddress(&pT,   g_T);
    cudaGetSymbolAddress(&pTk,  g_Tk);
    cudaGetSymbolAddress(&pZ,   g_Z);
    cudaGetSymbolAddress(&pKf,  g_Kf);
    cudaGetSymbolAddress(&pTmp, g_tmp);
    cudaGetSymbolAddress(&pDW,  g_DW);
    cudaGetSymbolAddress(&pDI,  g_DI);

    init_twiddles<<<64, 256>>>();
    prep_w<<<8192, 256>>>(w1r, w1i, w2r, w2i);

    // forward W-DFT as GEMM: [M x 256] @ [256 x 64]
    gemm2<NW, 64><<<dim3(1, (NBL * NC * NH) / 128), 128>>>(x, (const float*)pDW, (float*)pT);
    gemm2<NW, 64><<<dim3(1, (NC * NH) / 128),       128>>>(k, (const float*)pDW, (float*)pTk);

    // forward H-DFT
    fwdH<<<NC, 256>>>((const float*)pTk, (float*)pKf);
    fwdH<<<NBL * NC, 256>>>((const float*)pT, (float*)pZ);

    // per-mode conv + channel mix
    mix_modes<<<NP * NJ, 1024>>>();

    // inverse H-DFT
    invH<<<NBL * NC, 256>>>();

    // inverse W c2r as GEMM: [M x 64] @ [64 x 256] -> out
    gemm2<64, NW><<<dim3(NW / 64, (NBL * NC * NH) / 128), 128>>>((const float*)pTmp,
                                                                 (const float*)pDI, out);
}

// round 6
// speedup vs baseline: 1.3586x; 1.2057x over previous
#include <cuda_runtime.h>

// Problem constants
#define NBL 32   // B*L
#define NC  32   // channels
#define NH  128
#define NW  256
#define NJ  32   // kept W-modes
#define NP  64   // kept H-rows: {0..31, 96..127}
#define NBAT  1024          // x batches (bl*c)
#define NBATT 1056          // x + k batches

typedef unsigned long long u64;

// ---- packed fp32x2 helpers (FFMA2 is PTX-only) ----
__device__ __forceinline__ u64 dup2(float v) {
    u64 r; asm("mov.b64 %0,{%1,%1};" : "=l"(r) : "f"(v)); return r;
}
__device__ __forceinline__ void fma2(u64 &d, u64 a, u64 b) {
    asm("fma.rn.f32x2 %0,%1,%2,%0;" : "+l"(d) : "l"(a), "l"(b));
}
__device__ __forceinline__ float2 up2(u64 v) {
    float2 f; asm("mov.b64 {%0,%1},%2;" : "=f"(f.x), "=f"(f.y) : "l"(v)); return f;
}

// ---------------- scratch ----------------
// T layout: [m = batch*128+h][r = comp*32+j]   batch 0..1055 (x then k)
// Z / G layout: [batch][p][comp][j]
__device__ __align__(16) float g_T  [(size_t)NBATT*NH*64];
__device__ __align__(16) float g_Z  [(size_t)NBATT*NP*2*NJ];
__device__ __align__(16) float g_G  [(size_t)NBAT*NP*2*NJ];
__device__ __align__(16) float g_tmp[(size_t)NBAT*NH*64];
__device__ __align__(16) float g_DW [NW*64];      // fwd W-DFT  [w][r]
__device__ __align__(16) float g_CH2[65*NP];      // fwd H cos  [h'][p]   (h-paired)
__device__ __align__(16) float g_SH2[65*NP];      // fwd H sin  [h'][p]
__device__ __align__(16) float g_CI2[33*NH];      // inv H cos/H [r][h]   (p-paired)
__device__ __align__(16) float g_SI2[33*NH];      // inv H sin/H [r][h]
__device__ __align__(16) float g_DI [64*NW];      // inv W c2r  [r][w]
__device__ __align__(16) float g_Wmix[(size_t)NP*NJ*NC*NC*2];

__device__ __forceinline__ int row_of_p(int p) { return (p < 32) ? p : (64 + p); }

// ---------------- twiddle init ----------------
__global__ void init_twiddles() {
    int idx = blockIdx.x * blockDim.x + threadIdx.x;  // 16384 threads
    if (idx < NW * 64) {
        int w = idx >> 6, r = idx & 63, comp = r >> 5, j = r & 31;
        int t = (j * w) % NW;
        float s, c; sincospif(2.0f * (float)t / (float)NW, &s, &c);
        g_DW[idx] = comp ? -s : c;
    }
    if (idx < 65 * NP) {            // fwd H tables, h' = 0..64
        int h = idx / NP, p = idx % NP;
        int t = (row_of_p(p) * h) % NH;
        float s, c; sincospif(2.0f * (float)t / (float)NH, &s, &c);
        g_CH2[idx] = c; g_SH2[idx] = s;
    }
    if (idx < 33 * NH) {            // inv H tables, r = 0..32 (row r / row 96)
        int r = idx / NH, h = idx % NH;
        int t = (row_of_p(r) * h) % NH;   // r<32 -> row r ; r==32 -> row 96
        float s, c; sincospif(2.0f * (float)t / (float)NH, &s, &c);
        g_CI2[idx] = c * (1.0f / (float)NH);
        g_SI2[idx] = s * (1.0f / (float)NH);
    }
    if (idx < 64 * NW) {
        int r = idx >> 8, w = idx & 255, comp = r >> 5, j = r & 31;
        int t = (j * w) % NW;
        float s, c; sincospif(2.0f * (float)t / (float)NW, &s, &c);
        float v;
        if (comp == 0) v = ((j == 0) ? 1.0f : 2.0f) * (1.0f / (float)NW) * c;
        else           v = (j == 0) ? 0.0f : (-2.0f / (float)NW) * s;
        g_DI[idx] = v;
    }
}

// ---------------- weight transpose (coalesced reads, j fastest) ----------------
__global__ void prep_w(const float* __restrict__ w1r, const float* __restrict__ w1i,
                       const float* __restrict__ w2r, const float* __restrict__ w2i) {
    int idx = blockIdx.x * blockDim.x + threadIdx.x;
    if (idx >= NP * NJ * NC * NC) return;
    int j = idx & 31;
    int o = (idx >> 5) & 31;
    int c = (idx >> 10) & 31;
    int p = idx >> 15;
    int i = (p < 32) ? p : (p - 32);
    const float* wr = (p < 32) ? w1r : w2r;
    const float* wi = (p < 32) ? w1i : w2i;
    int widx = ((c * NC + o) * 32 + i) * 32 + j;      // contiguous in j
    size_t dst = ((size_t)(p * 32 + j) * NC * NC + c * NC + o) * 2;
    g_Wmix[dst + 0] = wr[widx];
    g_Wmix[dst + 1] = wi[widx];
}

// ---------------- FFMA2 GEMM: C[M,NDIM] = A[M,KDIM] * B[KDIM,NDIM] ----------------
// 128 threads, BM=128, BN=64, BK=32, 8x8 per-thread tile paired over n.
// Row-blocks < SPLIT read A0, >= SPLIT read A1 (k appended after x).
template<int KDIM, int NDIM>
__global__ __launch_bounds__(128, 3) void gemm2(const float* __restrict__ A0,
                                                const float* __restrict__ A1, int split,
                                                const float* __restrict__ Bm,
                                                float* __restrict__ Cm) {
    __shared__ float2 As2[32][129];
    __shared__ float  Bs[32][68];
    int by = blockIdx.y, n0 = blockIdx.x * 64;
    const float* Ab = (by < split) ? (A0 + (size_t)by * 128 * KDIM)
                                   : (A1 + (size_t)(by - split) * 128 * KDIM);
    int t = threadIdx.x;
    int tx = t & 7, ty = t >> 3;

    u64 acc[8][4];
#pragma unroll
    for (int i = 0; i < 8; i++)
#pragma unroll
        for (int m = 0; m < 4; m++) acc[i][m] = 0ull;

    for (int k0 = 0; k0 < KDIM; k0 += 32) {
#pragma unroll
        for (int rr = 0; rr < 8; rr++) {
            int row = ty + 16 * rr;
            float4 v = *(const float4*)(Ab + (size_t)row * KDIM + k0 + tx * 4);
            As2[tx * 4 + 0][row] = make_float2(v.x, v.x);
            As2[tx * 4 + 1][row] = make_float2(v.y, v.y);
            As2[tx * 4 + 2][row] = make_float2(v.z, v.z);
            As2[tx * 4 + 3][row] = make_float2(v.w, v.w);
        }
#pragma unroll
        for (int i = 0; i < 4; i++) {
            int f = t + 128 * i;
            int r = f >> 4, c = (f & 15) * 4;
            *(float4*)&Bs[r][c] = *(const float4*)(Bm + (size_t)(k0 + r) * NDIM + n0 + c);
        }
        __syncthreads();
#pragma unroll 8
        for (int kk = 0; kk < 32; kk++) {
            u64 b0 = *(const u64*)&Bs[kk][tx * 2];
            u64 b1 = *(const u64*)&Bs[kk][tx * 2 + 16];
            u64 b2 = *(const u64*)&Bs[kk][tx * 2 + 32];
            u64 b3 = *(const u64*)&Bs[kk][tx * 2 + 48];
#pragma unroll
            for (int i = 0; i < 8; i++) {
                u64 a = *(const u64*)&As2[kk][ty * 8 + i];
                fma2(acc[i][0], a, b0);
                fma2(acc[i][1], a, b1);
                fma2(acc[i][2], a, b2);
                fma2(acc[i][3], a, b3);
            }
        }
        __syncthreads();
    }
#pragma unroll
    for (int i = 0; i < 8; i++)
#pragma unroll
        for (int m = 0; m < 4; m++)
            *(float2*)&Cm[(size_t)((size_t)by * 128 + ty * 8 + i) * NDIM + n0 + tx * 2 + 16 * m] = up2(acc[i][m]);
}

// ---------------- forward H-DFT, h-paired: T[batch][h][r] -> Z[batch][p][comp][j] ----------------
// E[h'] = T(h')+T(128-h'), D[h'] = T(h')-T(128-h')  (h'=0,64: E=T, D mult by exact-0 sin)
// Zr(p) = sum_{h'=0..64} c*ETr + s*DTi ;  Zi(p) = sum c*ETi - s*DTr
__global__ __launch_bounds__(256) void fwdH(const float* __restrict__ Tin,
                                            float* __restrict__ Zout) {
    __shared__ float Es[65][68];
    __shared__ float Ds[65][68];
    int batch = blockIdx.x, t = threadIdx.x;
    const float* src = Tin + (size_t)batch * NH * 64;
    for (int f = t; f < 65 * 16; f += 256) {
        int r = f >> 4, c = (f & 15) * 4;
        float4 a = *(const float4*)(src + r * 64 + c);
        float4 b = make_float4(0.f, 0.f, 0.f, 0.f);
        if (r >= 1 && r <= 63) b = *(const float4*)(src + (128 - r) * 64 + c);
        *(float4*)&Es[r][c] = make_float4(a.x + b.x, a.y + b.y, a.z + b.z, a.w + b.w);
        *(float4*)&Ds[r][c] = make_float4(a.x - b.x, a.y - b.y, a.z - b.z, a.w - b.w);
    }
    __syncthreads();

    int p = t & 63, jg = t >> 6, j0 = jg * 8;
    u64 zr[4] = {0, 0, 0, 0}, zi[4] = {0, 0, 0, 0};
    for (int h = 0; h < 65; h++) {
        float ch = g_CH2[h * NP + p];
        float sh = g_SH2[h * NP + p];
        u64 cd = dup2(ch), sd = dup2(sh), nd = dup2(-sh);
#pragma unroll
        for (int m = 0; m < 4; m++) {
            u64 etr = *(const u64*)&Es[h][j0 + 2 * m];
            u64 eti = *(const u64*)&Es[h][32 + j0 + 2 * m];
            u64 dtr = *(const u64*)&Ds[h][j0 + 2 * m];
            u64 dti = *(const u64*)&Ds[h][32 + j0 + 2 * m];
            fma2(zr[m], cd, etr); fma2(zr[m], sd, dti);
            fma2(zi[m], cd, eti); fma2(zi[m], nd, dtr);
        }
    }
    float* dr = Zout + (((size_t)batch * NP + p) * 2 + 0) * NJ + j0;
    float* di = Zout + (((size_t)batch * NP + p) * 2 + 1) * NJ + j0;
#pragma unroll
    for (int m = 0; m < 4; m++) {
        *(float2*)&dr[2 * m] = up2(zr[m]);
        *(float2*)&di[2 * m] = up2(zi[m]);
    }
}

// ---------------- per-mode channel mix ----------------
__global__ __launch_bounds__(1024) void mix_modes() {
    int mode = blockIdx.x;          // p*32 + j
    int p = mode >> 5, j = mode & 31;
    __shared__ float2 zk[NC][NBL];
    __shared__ float2 ws[NC][NC];
    int t = threadIdx.x;
    {
        int c1 = t >> 5, lo = t & 31;
        int blc = lo * NC + c1;
        size_t zb = (((size_t)blc * NP + p) * 2) * NJ + j;
        float zr = g_Z[zb], zi = g_Z[zb + NJ];
        size_t kb = (((size_t)(NBAT + c1) * NP + p) * 2) * NJ + j;   // k batches appended
        float kr = g_Z[kb], ki = g_Z[kb + NJ];
        zk[c1][lo] = make_float2(zr * kr - zi * ki, zr * ki + zi * kr);
        ws[c1][lo] = ((const float2*)(g_Wmix + (size_t)mode * NC * NC * 2))[t];
    }
    __syncthreads();
    int o = t & 31, bl = t >> 5;
    float ar = 0.0f, ai = 0.0f;
#pragma unroll
    for (int c = 0; c < NC; c++) {
        float2 w = ws[c][o];
        float2 x = zk[c][bl];
        ar += w.x * x.x - w.y * x.y;
        ai += w.x * x.y + w.y * x.x;
    }
    size_t gb = (((size_t)(bl * NC + o) * NP + p) * 2) * NJ + j;
    g_G[gb] = ar; g_G[gb + NJ] = ai;
}

// ---------------- inverse H-DFT, p-paired: G[blo][p][comp][j] -> tmp[blo*128+h][r] ----------------
// E[r] = G(r)+G(64-r), D[r] = G(r)-G(64-r) for r=1..31;  r=0: E=D=G(0) (sin row exact 0);
// r=32: E=D=G(32) (row 96, single-row contribution is exactly the E=D form).
// tr(h) = sum_r ci*Er - si*Di ;  ti(h) = sum_r ci*Ei + si*Dr
__global__ __launch_bounds__(256) void invH() {
    __shared__ float Es[33][68];
    __shared__ float Ds[33][68];
    int blo = blockIdx.x, t = threadIdx.x;
    const float* src = g_G + (size_t)blo * NP * 64;
    for (int f = t; f < 33 * 16; f += 256) {
        int r = f >> 4, c = (f & 15) * 4;
        float4 a = *(const float4*)(src + r * 64 + c);
        if (r >= 1 && r <= 31) {
            float4 b = *(const float4*)(src + (64 - r) * 64 + c);
            *(float4*)&Es[r][c] = make_float4(a.x + b.x, a.y + b.y, a.z + b.z, a.w + b.w);
            *(float4*)&Ds[r][c] = make_float4(a.x - b.x, a.y - b.y, a.z - b.z, a.w - b.w);
        } else {
            *(float4*)&Es[r][c] = a;
            *(float4*)&Ds[r][c] = a;
        }
    }
    __syncthreads();

    int h = t & 127, q = t >> 7, j0 = q * 16;
    u64 tr[8], ti[8];
#pragma unroll
    for (int m = 0; m < 8; m++) { tr[m] = 0ull; ti[m] = 0ull; }
    for (int r = 0; r < 33; r++) {
        float ci = g_CI2[r * NH + h];
        float si = g_SI2[r * NH + h];
        u64 cd = dup2(ci), sd = dup2(si), nd = dup2(-si);
#pragma unroll
        for (int m = 0; m < 8; m++) {
            u64 er = *(const u64*)&Es[r][j0 + 2 * m];
            u64 ei = *(const u64*)&Es[r][32 + j0 + 2 * m];
            u64 dr = *(const u64*)&Ds[r][j0 + 2 * m];
            u64 di = *(const u64*)&Ds[r][32 + j0 + 2 * m];
            fma2(tr[m], cd, er); fma2(tr[m], nd, di);
            fma2(ti[m], cd, ei); fma2(ti[m], sd, dr);
        }
    }
    float* dst = g_tmp + ((size_t)blo * NH + h) * 64;
#pragma unroll
    for (int m = 0; m < 8; m++) {
        *(float2*)&dst[j0 + 2 * m]      = up2(tr[m]);
        *(float2*)&dst[32 + j0 + 2 * m] = up2(ti[m]);
    }
}

// ---------------- host launcher ----------------
extern "C" void kernel_launch(void* const* d_in, const int* in_sizes, int n_in,
                              void* d_out, int out_size) {
    const float* x   = (const float*)d_in[0];
    const float* k   = (const float*)d_in[1];
    const float* w1r = (const float*)d_in[2];
    const float* w1i = (const float*)d_in[3];
    const float* w2r = (const float*)d_in[4];
    const float* w2i = (const float*)d_in[5];
    float* out = (float*)d_out;
    (void)in_sizes; (void)n_in; (void)out_size;

    void *pT, *pZ, *pTmp, *pDW, *pDI;
    cudaGetSymbolAddress(&pT,   g_T);
    cudaGetSymbolAddress(&pZ,   g_Z);
    cudaGetSymbolAddress(&pTmp, g_tmp);
    cudaGetSymbolAddress(&pDW,  g_DW);
    cudaGetSymbolAddress(&pDI,  g_DI);

    init_twiddles<<<64, 256>>>();
    prep_w<<<8192, 256>>>(w1r, w1i, w2r, w2i);

    // forward W-DFT as GEMM over x (1024 row-blocks) + k (32 row-blocks appended)
    gemm2<NW, 64><<<dim3(1, NBATT), 128>>>(x, k, NBAT, (const float*)pDW, (float*)pT);

    // forward H-DFT over x + k batches
    fwdH<<<NBATT, 256>>>((const float*)pT, (float*)pZ);

    // per-mode conv + channel mix
    mix_modes<<<NP * NJ, 1024>>>();

    // inverse H-DFT
    invH<<<NBAT, 256>>>();

    // inverse W c2r as GEMM: [M x 64] @ [64 x 256] -> out
    gemm2<64, NW><<<dim3(NW / 64, NBAT), 128>>>((const float*)pTmp, (const float*)pTmp,
                                                NBAT, (const float*)pDI, out);
}

// round 8
// speedup vs baseline: 1.4304x; 1.0529x over previous
#include <cuda_runtime.h>

// Problem constants
#define NBL 32   // B*L
#define NC  32   // channels
#define NH  128
#define NW  256
#define NJ  32   // kept W-modes
#define NP  64   // kept H-rows: {0..31, 96..127}
#define NBAT  1024          // x batches (bl*c)
#define NBATT 1056          // x + k batches

typedef unsigned long long u64;

// ---- packed fp32x2 helpers (PTX-only; ptxas never auto-fuses) ----
__device__ __forceinline__ u64 dup2(float v) {
    u64 r; asm("mov.b64 %0,{%1,%1};" : "=l"(r) : "f"(v)); return r;
}
__device__ __forceinline__ void fma2(u64 &d, u64 a, u64 b) {
    asm("fma.rn.f32x2 %0,%1,%2,%0;" : "+l"(d) : "l"(a), "l"(b));
}
__device__ __forceinline__ u64 mul2(u64 a, u64 b) {
    u64 d; asm("mul.rn.f32x2 %0,%1,%2;" : "=l"(d) : "l"(a), "l"(b)); return d;
}
__device__ __forceinline__ float2 up2(u64 v) {
    float2 f; asm("mov.b64 {%0,%1},%2;" : "=f"(f.x), "=f"(f.y) : "l"(v)); return f;
}

// ---------------- scratch ----------------
// T / tmp layout: [m = batch*128+h][r = comp*32+j]
// Z / G layout: [batch][p][comp][j]
__device__ __align__(16) float g_T  [(size_t)NBATT*NH*64];
__device__ __align__(16) float g_Z  [(size_t)NBATT*NP*2*NJ];
__device__ __align__(16) float g_G  [(size_t)NBAT*NP*2*NJ];
__device__ __align__(16) float g_tmp[(size_t)NBAT*NH*64];
__device__ __align__(16) float g_DW [NW*64];      // fwd W-DFT  [w][r]
__device__ __align__(16) float g_DI [64*NW];      // inv W c2r  [r][w]
__device__ __align__(16) float g_Wr [(size_t)NP*NC*NC*NJ];   // [p][c][o][j]
__device__ __align__(16) float g_Wi [(size_t)NP*NC*NC*NJ];

// ---------------- twiddle init (DFT matrices only; H twiddles are in-kernel recurrences) ----
__global__ void init_twiddles() {
    int idx = blockIdx.x * blockDim.x + threadIdx.x;  // 16384 threads
    if (idx < NW * 64) {
        int w = idx >> 6, r = idx & 63, comp = r >> 5, j = r & 31;
        int t = (j * w) % NW;
        float s, c; sincospif(2.0f * (float)t / (float)NW, &s, &c);
        g_DW[idx] = comp ? -s : c;
    }
    if (idx < 64 * NW) {
        int r = idx >> 8, w = idx & 255, comp = r >> 5, j = r & 31;
        int t = (j * w) % NW;
        float s, c; sincospif(2.0f * (float)t / (float)NW, &s, &c);
        float v;
        if (comp == 0) v = ((j == 0) ? 1.0f : 2.0f) * (1.0f / (float)NW) * c;
        else           v = (j == 0) ? 0.0f : (-2.0f / (float)NW) * s;
        g_DI[idx] = v;
    }
}

// ---------------- weight planes: [c][o][i][j] -> Wr/Wi[p][c][o][j] (fully coalesced) ----
__global__ void prep_w(const float* __restrict__ w1r, const float* __restrict__ w1i,
                       const float* __restrict__ w2r, const float* __restrict__ w2i) {
    int idx4 = blockIdx.x * blockDim.x + threadIdx.x;   // 524288 float4 units
    if (idx4 >= NP * NC * NC * 8) return;
    int j4 = idx4 & 7;
    int o  = (idx4 >> 3) & 31;
    int c  = (idx4 >> 8) & 31;
    int p  = idx4 >> 13;
    int i  = (p < 32) ? p : (p - 32);
    const float* wr = (p < 32) ? w1r : w2r;
    const float* wi = (p < 32) ? w1i : w2i;
    size_t srcb = ((size_t)(c * NC + o) * 32 + i) * 32 + j4 * 4;
    size_t dstb = (((size_t)(p * NC + c) * NC + o) * 32) + j4 * 4;
    *(float4*)&g_Wr[dstb] = *(const float4*)&wr[srcb];
    *(float4*)&g_Wi[dstb] = *(const float4*)&wi[srcb];
}

// ---------------- FFMA2 GEMM: C[M,NDIM] = A[M,KDIM] * B[KDIM,NDIM] ----------------
template<int KDIM, int NDIM>
__global__ __launch_bounds__(128, 3) void gemm2(const float* __restrict__ A0,
                                                const float* __restrict__ A1, int split,
                                                const float* __restrict__ Bm,
                                                float* __restrict__ Cm) {
    __shared__ __align__(16) float2 As2[32][130];
    __shared__ float  Bs[32][68];
    int by = blockIdx.y, n0 = blockIdx.x * 64;
    const float* Ab = (by < split) ? (A0 + (size_t)by * 128 * KDIM)
                                   : (A1 + (size_t)(by - split) * 128 * KDIM);
    int t = threadIdx.x;
    int tx = t & 7, ty = t >> 3;

    u64 acc[8][4];
#pragma unroll
    for (int i = 0; i < 8; i++)
#pragma unroll
        for (int m = 0; m < 4; m++) acc[i][m] = 0ull;

    for (int k0 = 0; k0 < KDIM; k0 += 32) {
#pragma unroll
        for (int rr = 0; rr < 8; rr++) {
            int row = ty + 16 * rr;
            float4 v = *(const float4*)(Ab + (size_t)row * KDIM + k0 + tx * 4);
            As2[tx * 4 + 0][row] = make_float2(v.x, v.x);
            As2[tx * 4 + 1][row] = make_float2(v.y, v.y);
            As2[tx * 4 + 2][row] = make_float2(v.z, v.z);
            As2[tx * 4 + 3][row] = make_float2(v.w, v.w);
        }
#pragma unroll
        for (int i = 0; i < 4; i++) {
            int f = t + 128 * i;
            int r = f >> 4, c = (f & 15) * 4;
            *(float4*)&Bs[r][c] = *(const float4*)(Bm + (size_t)(k0 + r) * NDIM + n0 + c);
        }
        __syncthreads();
#pragma unroll 8
        for (int kk = 0; kk < 32; kk++) {
            u64 b0 = *(const u64*)&Bs[kk][tx * 2];
            u64 b1 = *(const u64*)&Bs[kk][tx * 2 + 16];
            u64 b2 = *(const u64*)&Bs[kk][tx * 2 + 32];
            u64 b3 = *(const u64*)&Bs[kk][tx * 2 + 48];
            const ulonglong2* ap = (const ulonglong2*)&As2[kk][ty * 8];
            ulonglong2 a01 = ap[0], a23 = ap[1], a45 = ap[2], a67 = ap[3];
            u64 av[8] = {a01.x, a01.y, a23.x, a23.y, a45.x, a45.y, a67.x, a67.y};
#pragma unroll
            for (int i = 0; i < 8; i++) {
                fma2(acc[i][0], av[i], b0);
                fma2(acc[i][1], av[i], b1);
                fma2(acc[i][2], av[i], b2);
                fma2(acc[i][3], av[i], b3);
            }
        }
        __syncthreads();
    }
#pragma unroll
    for (int i = 0; i < 8; i++)
#pragma unroll
        for (int m = 0; m < 4; m++)
            *(float2*)&Cm[(size_t)((size_t)by * 128 + ty * 8 + i) * NDIM + n0 + tx * 2 + 16 * m] = up2(acc[i][m]);
}

// ---------------- forward H-DFT v2: register-blocked, recurrence twiddles ----------------
// Staged (h'=0..64, pairing h & 128-h):  SE[0]=Er, SE[1]=Ei, SD[0]=Dti, SD[1]=nDtr
// Zr(p) = sum c·Er + s·Dti ;  Zi(p) = sum c·Ei + s·nDtr   (c,s by per-p rotation recurrence)
__global__ __launch_bounds__(128) void fwdH2(const float* __restrict__ Tin,
                                             float* __restrict__ Zout) {
    __shared__ __align__(16) float SE[2][65][36];
    __shared__ __align__(16) float SD[2][65][36];
    int batch = blockIdx.x, t = threadIdx.x;
    const float* src = Tin + (size_t)batch * NH * 64;
    for (int f = t; f < 65 * 16; f += 128) {
        int r = f >> 4, c4 = (f & 15) * 4;
        int comp = c4 >> 5, cc = c4 & 31;
        float4 a = *(const float4*)(src + r * 64 + c4);
        float4 b = make_float4(0.f, 0.f, 0.f, 0.f);
        if (r >= 1 && r <= 63) b = *(const float4*)(src + (128 - r) * 64 + c4);
        float4 e = make_float4(a.x + b.x, a.y + b.y, a.z + b.z, a.w + b.w);
        float4 d;
        if (comp == 0) d = make_float4(b.x - a.x, b.y - a.y, b.z - a.z, b.w - a.w);  // nDtr
        else           d = make_float4(a.x - b.x, a.y - b.y, a.z - b.z, a.w - b.w);  // Dti
        *(float4*)&SE[comp][r][cc] = e;
        *(float4*)&SD[comp ^ 1][r][cc] = d;
    }
    __syncthreads();

    int tx = t & 7, ty = t >> 3;
    int compo = tx >> 2, bf = (tx & 3) * 8;
    const float* pe = &SE[compo][0][bf];
    const float* pd = &SD[compo][0][bf];

    u64 cd[4], sd[4], c1[4], s1[4], ns1[4];
#pragma unroll
    for (int i = 0; i < 4; i++) {
        int p = ty * 4 + i;
        int row = (p < 32) ? p : 64 + p;
        float ss, cc2; sincospif((float)row * (1.0f / 64.0f), &ss, &cc2);
        c1[i] = dup2(cc2); s1[i] = dup2(ss); ns1[i] = dup2(-ss);
        cd[i] = dup2(1.0f); sd[i] = dup2(0.0f);
    }
    u64 acc[4][4];
#pragma unroll
    for (int i = 0; i < 4; i++)
#pragma unroll
        for (int m = 0; m < 4; m++) acc[i][m] = 0ull;

    for (int h = 0; h < 65; h++) {
        ulonglong2 e01 = *(const ulonglong2*)(pe + h * 36);
        ulonglong2 e23 = *(const ulonglong2*)(pe + h * 36 + 4);
        ulonglong2 d01 = *(const ulonglong2*)(pd + h * 36);
        ulonglong2 d23 = *(const ulonglong2*)(pd + h * 36 + 4);
#pragma unroll
        for (int i = 0; i < 4; i++) {
            fma2(acc[i][0], cd[i], e01.x); fma2(acc[i][1], cd[i], e01.y);
            fma2(acc[i][2], cd[i], e23.x); fma2(acc[i][3], cd[i], e23.y);
            fma2(acc[i][0], sd[i], d01.x); fma2(acc[i][1], sd[i], d01.y);
            fma2(acc[i][2], sd[i], d23.x); fma2(acc[i][3], sd[i], d23.y);
            u64 nc = mul2(cd[i], c1[i]); fma2(nc, sd[i], ns1[i]);
            u64 ns = mul2(sd[i], c1[i]); fma2(ns, cd[i], s1[i]);
            cd[i] = nc; sd[i] = ns;
        }
    }
#pragma unroll
    for (int i = 0; i < 4; i++) {
        int p = ty * 4 + i;
        float* dst = Zout + (((size_t)batch * NP + p) * 2 + compo) * NJ + (tx & 3) * 8;
        *(ulonglong2*)dst       = make_ulonglong2(acc[i][0], acc[i][1]);
        *(ulonglong2*)(dst + 4) = make_ulonglong2(acc[i][2], acc[i][3]);
    }
}

// ---------------- per-mode channel mix v2: packed along j-pairs ----------------
// block = (p, jpair); thread = 2 bl x 4 o; G(bl,o) = sum_c zk(bl,c) * W(c,o) elementwise in j
__global__ __launch_bounds__(128) void mix2() {
    int blk = blockIdx.x;            // 64p * 16jp
    int p = blk >> 4, jp = blk & 15; // j0 = jp*2
    __shared__ float2 s_zkr[NC][33];
    __shared__ float2 s_zki[NC][33];
    __shared__ float2 s_wr [NC][33];
    __shared__ float2 s_wi [NC][33];
    __shared__ float2 s_nwi[NC][33];
    int t = threadIdx.x;
    for (int e = t; e < 1024; e += 128) {
        int c = e >> 5, bl = e & 31;
        int blc = bl * NC + c;
        const float* zb = g_Z + (((size_t)blc * NP + p) * 2) * NJ + jp * 2;
        float2 zr = *(const float2*)zb;
        float2 zi = *(const float2*)(zb + NJ);
        const float* kb = g_Z + (((size_t)(NBAT + c) * NP + p) * 2) * NJ + jp * 2;
        float2 kr = *(const float2*)kb;
        float2 ki = *(const float2*)(kb + NJ);
        s_zkr[c][bl] = make_float2(zr.x * kr.x - zi.x * ki.x, zr.y * kr.y - zi.y * ki.y);
        s_zki[c][bl] = make_float2(zr.x * ki.x + zi.x * kr.x, zr.y * ki.y + zi.y * kr.y);
    }
    for (int e = t; e < 1024; e += 128) {
        int c = e >> 5, o = e & 31;
        size_t wb = (((size_t)(p * NC + c) * NC + o) * 32) + jp * 2;
        float2 wr = *(const float2*)&g_Wr[wb];
        float2 wi = *(const float2*)&g_Wi[wb];
        s_wr[c][o] = wr; s_wi[c][o] = wi;
        s_nwi[c][o] = make_float2(-wi.x, -wi.y);
    }
    __syncthreads();

    int op = t & 7, blp = t >> 3;    // o = op*4+b, bl = blp*2+a
    u64 ar[2][4], ai[2][4];
#pragma unroll
    for (int a = 0; a < 2; a++)
#pragma unroll
        for (int b = 0; b < 4; b++) { ar[a][b] = 0ull; ai[a][b] = 0ull; }

#pragma unroll 4
    for (int c = 0; c < NC; c++) {
        u64 xr[2], xi[2], wr4[4], wi4[4], nw4[4];
#pragma unroll
        for (int a = 0; a < 2; a++) {
            xr[a] = *(const u64*)&s_zkr[c][blp * 2 + a];
            xi[a] = *(const u64*)&s_zki[c][blp * 2 + a];
        }
#pragma unroll
        for (int b = 0; b < 4; b++) {
            wr4[b] = *(const u64*)&s_wr [c][op * 4 + b];
            wi4[b] = *(const u64*)&s_wi [c][op * 4 + b];
            nw4[b] = *(const u64*)&s_nwi[c][op * 4 + b];
        }
#pragma unroll
        for (int a = 0; a < 2; a++)
#pragma unroll
            for (int b = 0; b < 4; b++) {
                fma2(ar[a][b], xr[a], wr4[b]); fma2(ar[a][b], xi[a], nw4[b]);
                fma2(ai[a][b], xi[a], wr4[b]); fma2(ai[a][b], xr[a], wi4[b]);
            }
    }
#pragma unroll
    for (int a = 0; a < 2; a++)
#pragma unroll
        for (int b = 0; b < 4; b++) {
            int blc = (blp * 2 + a) * NC + op * 4 + b;
            float* gb = g_G + (((size_t)blc * NP + p) * 2) * NJ + jp * 2;
            *(float2*)gb        = up2(ar[a][b]);
            *(float2*)(gb + NJ) = up2(ai[a][b]);
        }
}

// ---------------- inverse H-DFT v2: register-blocked, recurrence twiddles ----------------
// Staged (r=0..32):  SE[0]=Er, SE[1]=Ei, SD[0]=nDi, SD[1]=Dr  (r=0, r=32 special)
// tr(h) = sum_r c·Er + s·nDi ;  ti(h) = sum_r c·Ei + s·Dr   (c,s by per-h rotation)
__global__ __launch_bounds__(256) void invH2() {
    __shared__ __align__(16) float SE[2][33][36];
    __shared__ __align__(16) float SD[2][33][36];
    int blo = blockIdx.x, t = threadIdx.x;
    const float* src = g_G + (size_t)blo * NP * 64;
    for (int f = t; f < 33 * 16; f += 256) {
        int r = f >> 4, c4 = (f & 15) * 4;
        int comp = c4 >> 5, cc = c4 & 31;
        float4 a = *(const float4*)(src + r * 64 + c4);
        float4 e, d;
        if (r == 0) {
            e = a; d = make_float4(0.f, 0.f, 0.f, 0.f);
        } else if (r == 32) {
            e = a;
            if (comp == 0) d = make_float4(-a.x, -a.y, -a.z, -a.w);  // Dr = -Gr (row 96)
            else           d = a;                                     // nDi = +Gi
        } else {
            float4 b = *(const float4*)(src + (64 - r) * 64 + c4);
            e = make_float4(a.x + b.x, a.y + b.y, a.z + b.z, a.w + b.w);
            if (comp == 0) d = make_float4(a.x - b.x, a.y - b.y, a.z - b.z, a.w - b.w);  // Dr
            else           d = make_float4(b.x - a.x, b.y - a.y, b.z - a.z, b.w - a.w);  // nDi
        }
        *(float4*)&SE[comp][r][cc] = e;
        *(float4*)&SD[comp ^ 1][r][cc] = d;
    }
    __syncthreads();

    int tx = t & 7, ty = t >> 3;       // ty 0..31
    int compo = tx >> 2, bf = (tx & 3) * 8;
    const float* pe = &SE[compo][0][bf];
    const float* pd = &SD[compo][0][bf];

    u64 cd[4], sd[4], c1[4], s1[4], ns1[4];
#pragma unroll
    for (int i = 0; i < 4; i++) {
        int h = ty * 4 + i;
        float ss, cc2; sincospif((float)h * (1.0f / 64.0f), &ss, &cc2);
        c1[i] = dup2(cc2); s1[i] = dup2(ss); ns1[i] = dup2(-ss);
        cd[i] = dup2(1.0f); sd[i] = dup2(0.0f);
    }
    u64 acc[4][4];
#pragma unroll
    for (int i = 0; i < 4; i++)
#pragma unroll
        for (int m = 0; m < 4; m++) acc[i][m] = 0ull;

    for (int r = 0; r < 33; r++) {
        ulonglong2 e01 = *(const ulonglong2*)(pe + r * 36);
        ulonglong2 e23 = *(const ulonglong2*)(pe + r * 36 + 4);
        ulonglong2 d01 = *(const ulonglong2*)(pd + r * 36);
        ulonglong2 d23 = *(const ulonglong2*)(pd + r * 36 + 4);
#pragma unroll
        for (int i = 0; i < 4; i++) {
            fma2(acc[i][0], cd[i], e01.x); fma2(acc[i][1], cd[i], e01.y);
            fma2(acc[i][2], cd[i], e23.x); fma2(acc[i][3], cd[i], e23.y);
            fma2(acc[i][0], sd[i], d01.x); fma2(acc[i][1], sd[i], d01.y);
            fma2(acc[i][2], sd[i], d23.x); fma2(acc[i][3], sd[i], d23.y);
            u64 nc = mul2(cd[i], c1[i]); fma2(nc, sd[i], ns1[i]);
            u64 ns = mul2(sd[i], c1[i]); fma2(ns, cd[i], s1[i]);
            cd[i] = nc; sd[i] = ns;
        }
    }
    u64 sc = dup2(1.0f / 128.0f);
#pragma unroll
    for (int i = 0; i < 4; i++) {
        int h = ty * 4 + i;
        float* dst = g_tmp + ((size_t)blo * NH + h) * 64 + compo * 32 + (tx & 3) * 8;
        *(ulonglong2*)dst       = make_ulonglong2(mul2(acc[i][0], sc), mul2(acc[i][1], sc));
        *(ulonglong2*)(dst + 4) = make_ulonglong2(mul2(acc[i][2], sc), mul2(acc[i][3], sc));
    }
}

// ---------------- host launcher ----------------
extern "C" void kernel_launch(void* const* d_in, const int* in_sizes, int n_in,
                              void* d_out, int out_size) {
    const float* x   = (const float*)d_in[0];
    const float* k   = (const float*)d_in[1];
    const float* w1r = (const float*)d_in[2];
    const float* w1i = (const float*)d_in[3];
    const float* w2r = (const float*)d_in[4];
    const float* w2i = (const float*)d_in[5];
    float* out = (float*)d_out;
    (void)in_sizes; (void)n_in; (void)out_size;

    void *pT, *pZ, *pTmp, *pDW, *pDI;
    cudaGetSymbolAddress(&pT,   g_T);
    cudaGetSymbolAddress(&pZ,   g_Z);
    cudaGetSymbolAddress(&pTmp, g_tmp);
    cudaGetSymbolAddress(&pDW,  g_DW);
    cudaGetSymbolAddress(&pDI,  g_DI);

    init_twiddles<<<64, 256>>>();
    prep_w<<<2048, 256>>>(w1r, w1i, w2r, w2i);

    // forward W-DFT as GEMM over x (1024 row-blocks) + k (32 appended)
    gemm2<NW, 64><<<dim3(1, NBATT), 128>>>(x, k, NBAT, (const float*)pDW, (float*)pT);

    // forward H-DFT over x + k batches
    fwdH2<<<NBATT, 128>>>((const float*)pT, (float*)pZ);

    // per-mode conv + channel mix (packed over j-pairs)
    mix2<<<NP * 16, 128>>>();

    // inverse H-DFT
    invH2<<<NBAT, 256>>>();

    // inverse W c2r as GEMM: [M x 64] @ [64 x 256] -> out
    gemm2<64, NW><<<dim3(NW / 64, NBAT), 128>>>((const float*)pTmp, (const float*)pTmp,
                                                NBAT, (const float*)pDI, out);
}

// round 10
// speedup vs baseline: 1.4856x; 1.0386x over previous
#include <cuda_runtime.h>

// Problem constants
#define NBL 32   // B*L
#define NC  32   // channels
#define NH  128
#define NW  256
#define NJ  32   // kept W-modes
#define NP  64   // kept H-rows: {0..31, 96..127}
#define NBAT  1024          // x batches (bl*c)
#define NBATT 1056          // x + k batches

typedef unsigned long long u64;

// ---- packed fp32x2 helpers (PTX-only; ptxas never auto-fuses) ----
__device__ __forceinline__ u64 dup2(float v) {
    u64 r; asm("mov.b64 %0,{%1,%1};" : "=l"(r) : "f"(v)); return r;
}
__device__ __forceinline__ u64 pack2(float a, float b) {
    u64 r; asm("mov.b64 %0,{%1,%2};" : "=l"(r) : "f"(a), "f"(b)); return r;
}
__device__ __forceinline__ void fma2(u64 &d, u64 a, u64 b) {
    asm("fma.rn.f32x2 %0,%1,%2,%0;" : "+l"(d) : "l"(a), "l"(b));
}
__device__ __forceinline__ u64 mul2(u64 a, u64 b) {
    u64 d; asm("mul.rn.f32x2 %0,%1,%2;" : "=l"(d) : "l"(a), "l"(b)); return d;
}
__device__ __forceinline__ float2 up2(u64 v) {
    float2 f; asm("mov.b64 {%0,%1},%2;" : "=f"(f.x), "=f"(f.y) : "l"(v)); return f;
}

// ---------------- scratch ----------------
// T / tmp layout: [m = batch*128+h][r = comp*32+j]
// Z / G layout: [batch][p][comp][j]
__device__ __align__(16) float g_T  [(size_t)NBATT*NH*64];
__device__ __align__(16) float g_Z  [(size_t)NBATT*NP*2*NJ];
__device__ __align__(16) float g_G  [(size_t)NBAT*NP*2*NJ];
__device__ __align__(16) float g_tmp[(size_t)NBAT*NH*64];
__device__ __align__(16) float g_DW [NW*64];      // fwd W-DFT  [w][r]  (r<32 cos, r>=32 -sin)
__device__ __align__(16) float g_DI [64*NW];      // inv W c2r  [r][w]
__device__ __align__(16) float g_Wr [(size_t)NP*NC*NC*NJ];   // [p][c][o][j]
__device__ __align__(16) float g_Wi [(size_t)NP*NC*NC*NJ];

// ---------------- twiddle init (DFT matrices; H twiddles are in-kernel recurrences) ----
__global__ void init_twiddles() {
    int idx = blockIdx.x * blockDim.x + threadIdx.x;  // 16384 threads
    if (idx < NW * 64) {
        int w = idx >> 6, r = idx & 63, comp = r >> 5, j = r & 31;
        int t = (j * w) % NW;
        float s, c; sincospif(2.0f * (float)t / (float)NW, &s, &c);
        g_DW[idx] = comp ? -s : c;
    }
    if (idx < 64 * NW) {
        int r = idx >> 8, w = idx & 255, comp = r >> 5, j = r & 31;
        int t = (j * w) % NW;
        float s, c; sincospif(2.0f * (float)t / (float)NW, &s, &c);
        float v;
        if (comp == 0) v = ((j == 0) ? 1.0f : 2.0f) * (1.0f / (float)NW) * c;
        else           v = (j == 0) ? 0.0f : (-2.0f / (float)NW) * s;
        g_DI[idx] = v;
    }
}

// ---------------- weight planes: [c][o][i][j] -> Wr/Wi[p][c][o][j] (fully coalesced) ----
__global__ void prep_w(const float* __restrict__ w1r, const float* __restrict__ w1i,
                       const float* __restrict__ w2r, const float* __restrict__ w2i) {
    int idx4 = blockIdx.x * blockDim.x + threadIdx.x;   // 524288 float4 units
    if (idx4 >= NP * NC * NC * 8) return;
    int j4 = idx4 & 7;
    int o  = (idx4 >> 3) & 31;
    int c  = (idx4 >> 8) & 31;
    int p  = idx4 >> 13;
    int i  = (p < 32) ? p : (p - 32);
    const float* wr = (p < 32) ? w1r : w2r;
    const float* wi = (p < 32) ? w1i : w2i;
    size_t srcb = ((size_t)(c * NC + o) * 32 + i) * 32 + j4 * 4;
    size_t dstb = (((size_t)(p * NC + c) * NC + o) * 32) + j4 * 4;
    *(float4*)&g_Wr[dstb] = *(const float4*)&wr[srcb];
    *(float4*)&g_Wi[dstb] = *(const float4*)&wi[srcb];
}

// ---------------- forward W-DFT, mirror-folded: [128 rows x 256] -> [128 x 64] ----------------
// T_cos(j) = sum_{k=0..127} E[k] Bc[k][j] + x[128](-1)^j    (E[0]=2x0, Bc[0] pre-halved)
// T_sin(j) = sum_{k=0..127} D[k] Bs[k][j]                   (D[0]=0)
// B tiles use row stride 34 floats (136 B): 8B-aligned for LDS.64 at every k (33 trapped).
__global__ __launch_bounds__(128, 3) void gemm_fwd(const float* __restrict__ A0,
                                                   const float* __restrict__ A1, int split,
                                                   float* __restrict__ Cm) {
    extern __shared__ __align__(16) float sm[];
    float2* Es2 = (float2*)sm;               // [16][130]
    float2* Ds2 = Es2 + 16 * 130;            // [16][130]
    float*  Bc  = (float*)(Ds2 + 16 * 130);  // [128][34]
    float*  Bs  = Bc + 128 * 34;             // [128][34]
    float*  e128s = Bs + 128 * 34;           // [128]

    int by = blockIdx.x;
    const float* Ab = (by < split) ? (A0 + (size_t)by * 128 * NW)
                                   : (A1 + (size_t)(by - split) * 128 * NW);
    int t = threadIdx.x;
    int tx = t & 7, ty = t >> 3;

    // stage B (once): Bc[k][j] = DW[k][j] (k=0 halved); Bs[k][j] = DW[k][32+j]
    for (int f = t; f < 128 * 32; f += 128) {
        int k = f >> 5, j = f & 31;
        float bc = g_DW[k * 64 + j];
        Bc[k * 34 + j] = (k == 0) ? 0.5f * bc : bc;
        Bs[k * 34 + j] = g_DW[k * 64 + 32 + j];
    }
    // stash x[row][128]
    e128s[t] = Ab[(size_t)t * NW + 128];

    u64 acc[8][4];
#pragma unroll
    for (int i = 0; i < 8; i++)
#pragma unroll
        for (int m = 0; m < 4; m++) acc[i][m] = 0ull;

    for (int c0 = 0; c0 < 128; c0 += 16) {
        __syncthreads();
        // stage E/D for k in [c0, c0+16)
#pragma unroll
        for (int q = 0; q < 4; q++) {
            int f = t + 128 * q;             // 512 float4 units: row*4 + fc
            int row = f >> 2, fc = f & 3;
            const float* xr = Ab + (size_t)row * NW;
            float4 v = *(const float4*)(xr + c0 + fc * 4);
            float mv[4];
#pragma unroll
            for (int e = 0; e < 4; e++) {
                int k = c0 + fc * 4 + e;
                mv[e] = xr[(256 - k) & 255];
            }
            float ve[4] = {v.x, v.y, v.z, v.w};
#pragma unroll
            for (int e = 0; e < 4; e++) {
                int kk = fc * 4 + e;
                float ev = ve[e] + mv[e];
                float dv = ve[e] - mv[e];
                Es2[kk * 130 + row] = make_float2(ev, ev);
                Ds2[kk * 130 + row] = make_float2(dv, dv);
            }
        }
        __syncthreads();
#pragma unroll
        for (int kk = 0; kk < 16; kk++) {
            int kg = c0 + kk;
            u64 bc0 = *(const u64*)&Bc[kg * 34 + tx * 2];
            u64 bc1 = *(const u64*)&Bc[kg * 34 + tx * 2 + 16];
            u64 bs0 = *(const u64*)&Bs[kg * 34 + tx * 2];
            u64 bs1 = *(const u64*)&Bs[kg * 34 + tx * 2 + 16];
            const ulonglong2* pe = (const ulonglong2*)&Es2[kk * 130 + ty * 8];
            const ulonglong2* pd = (const ulonglong2*)&Ds2[kk * 130 + ty * 8];
            ulonglong2 e01 = pe[0], e23 = pe[1], e45 = pe[2], e67 = pe[3];
            ulonglong2 d01 = pd[0], d23 = pd[1], d45 = pd[2], d67 = pd[3];
            u64 aE[8] = {e01.x, e01.y, e23.x, e23.y, e45.x, e45.y, e67.x, e67.y};
            u64 aD[8] = {d01.x, d01.y, d23.x, d23.y, d45.x, d45.y, d67.x, d67.y};
#pragma unroll
            for (int i = 0; i < 8; i++) {
                fma2(acc[i][0], aE[i], bc0);
                fma2(acc[i][1], aE[i], bc1);
                fma2(acc[i][2], aD[i], bs0);
                fma2(acc[i][3], aD[i], bs1);
            }
        }
    }
    // epilogue: add x[128]*(-1)^j to cos accs; write out
    u64 PM1 = pack2(1.0f, -1.0f);
#pragma unroll
    for (int i = 0; i < 8; i++) {
        u64 e2 = dup2(e128s[ty * 8 + i]);
        fma2(acc[i][0], e2, PM1);
        fma2(acc[i][1], e2, PM1);
        float* dst = Cm + (size_t)((size_t)by * 128 + ty * 8 + i) * 64;
        *(float2*)&dst[tx * 2]      = up2(acc[i][0]);
        *(float2*)&dst[tx * 2 + 16] = up2(acc[i][1]);
        *(float2*)&dst[32 + tx * 2]      = up2(acc[i][2]);
        *(float2*)&dst[48 + tx * 2]      = up2(acc[i][3]);
    }
}

// ---------------- forward H-DFT v2: register-blocked, recurrence twiddles ----------------
__global__ __launch_bounds__(128) void fwdH2(const float* __restrict__ Tin,
                                             float* __restrict__ Zout) {
    __shared__ __align__(16) float SE[2][65][36];
    __shared__ __align__(16) float SD[2][65][36];
    int batch = blockIdx.x, t = threadIdx.x;
    const float* src = Tin + (size_t)batch * NH * 64;
    for (int f = t; f < 65 * 16; f += 128) {
        int r = f >> 4, c4 = (f & 15) * 4;
        int comp = c4 >> 5, cc = c4 & 31;
        float4 a = *(const float4*)(src + r * 64 + c4);
        float4 b = make_float4(0.f, 0.f, 0.f, 0.f);
        if (r >= 1 && r <= 63) b = *(const float4*)(src + (128 - r) * 64 + c4);
        float4 e = make_float4(a.x + b.x, a.y + b.y, a.z + b.z, a.w + b.w);
        float4 d;
        if (comp == 0) d = make_float4(b.x - a.x, b.y - a.y, b.z - a.z, b.w - a.w);  // nDtr
        else           d = make_float4(a.x - b.x, a.y - b.y, a.z - b.z, a.w - b.w);  // Dti
        *(float4*)&SE[comp][r][cc] = e;
        *(float4*)&SD[comp ^ 1][r][cc] = d;
    }
    __syncthreads();

    int tx = t & 7, ty = t >> 3;
    int compo = tx >> 2, bf = (tx & 3) * 8;
    const float* pe = &SE[compo][0][bf];
    const float* pd = &SD[compo][0][bf];

    u64 cd[4], sd[4], c1[4], s1[4], ns1[4];
#pragma unroll
    for (int i = 0; i < 4; i++) {
        int p = ty * 4 + i;
        int row = (p < 32) ? p : 64 + p;
        float ss, cc2; sincospif((float)row * (1.0f / 64.0f), &ss, &cc2);
        c1[i] = dup2(cc2); s1[i] = dup2(ss); ns1[i] = dup2(-ss);
        cd[i] = dup2(1.0f); sd[i] = dup2(0.0f);
    }
    u64 acc[4][4];
#pragma unroll
    for (int i = 0; i < 4; i++)
#pragma unroll
        for (int m = 0; m < 4; m++) acc[i][m] = 0ull;

    for (int h = 0; h < 65; h++) {
        ulonglong2 e01 = *(const ulonglong2*)(pe + h * 36);
        ulonglong2 e23 = *(const ulonglong2*)(pe + h * 36 + 4);
        ulonglong2 d01 = *(const ulonglong2*)(pd + h * 36);
        ulonglong2 d23 = *(const ulonglong2*)(pd + h * 36 + 4);
#pragma unroll
        for (int i = 0; i < 4; i++) {
            fma2(acc[i][0], cd[i], e01.x); fma2(acc[i][1], cd[i], e01.y);
            fma2(acc[i][2], cd[i], e23.x); fma2(acc[i][3], cd[i], e23.y);
            fma2(acc[i][0], sd[i], d01.x); fma2(acc[i][1], sd[i], d01.y);
            fma2(acc[i][2], sd[i], d23.x); fma2(acc[i][3], sd[i], d23.y);
            u64 nc = mul2(cd[i], c1[i]); fma2(nc, sd[i], ns1[i]);
            u64 ns = mul2(sd[i], c1[i]); fma2(ns, cd[i], s1[i]);
            cd[i] = nc; sd[i] = ns;
        }
    }
#pragma unroll
    for (int i = 0; i < 4; i++) {
        int p = ty * 4 + i;
        float* dst = Zout + (((size_t)batch * NP + p) * 2 + compo) * NJ + (tx & 3) * 8;
        *(ulonglong2*)dst       = make_ulonglong2(acc[i][0], acc[i][1]);
        *(ulonglong2*)(dst + 4) = make_ulonglong2(acc[i][2], acc[i][3]);
    }
}

// ---------------- per-mode channel mix v2: packed along j-pairs ----------------
__global__ __launch_bounds__(128) void mix2() {
    int blk = blockIdx.x;            // 64p * 16jp
    int p = blk >> 4, jp = blk & 15;
    __shared__ float2 s_zkr[NC][33];
    __shared__ float2 s_zki[NC][33];
    __shared__ float2 s_wr [NC][33];
    __shared__ float2 s_wi [NC][33];
    __shared__ float2 s_nwi[NC][33];
    int t = threadIdx.x;
    for (int e = t; e < 1024; e += 128) {
        int c = e >> 5, bl = e & 31;
        int blc = bl * NC + c;
        const float* zb = g_Z + (((size_t)blc * NP + p) * 2) * NJ + jp * 2;
        float2 zr = *(const float2*)zb;
        float2 zi = *(const float2*)(zb + NJ);
        const float* kb = g_Z + (((size_t)(NBAT + c) * NP + p) * 2) * NJ + jp * 2;
        float2 kr = *(const float2*)kb;
        float2 ki = *(const float2*)(kb + NJ);
        s_zkr[c][bl] = make_float2(zr.x * kr.x - zi.x * ki.x, zr.y * kr.y - zi.y * ki.y);
        s_zki[c][bl] = make_float2(zr.x * ki.x + zi.x * kr.x, zr.y * ki.y + zi.y * kr.y);
    }
    for (int e = t; e < 1024; e += 128) {
        int c = e >> 5, o = e & 31;
        size_t wb = (((size_t)(p * NC + c) * NC + o) * 32) + jp * 2;
        float2 wr = *(const float2*)&g_Wr[wb];
        float2 wi = *(const float2*)&g_Wi[wb];
        s_wr[c][o] = wr; s_wi[c][o] = wi;
        s_nwi[c][o] = make_float2(-wi.x, -wi.y);
    }
    __syncthreads();

    int op = t & 7, blp = t >> 3;
    u64 ar[2][4], ai[2][4];
#pragma unroll
    for (int a = 0; a < 2; a++)
#pragma unroll
        for (int b = 0; b < 4; b++) { ar[a][b] = 0ull; ai[a][b] = 0ull; }

#pragma unroll 4
    for (int c = 0; c < NC; c++) {
        u64 xr[2], xi[2], wr4[4], wi4[4], nw4[4];
#pragma unroll
        for (int a = 0; a < 2; a++) {
            xr[a] = *(const u64*)&s_zkr[c][blp * 2 + a];
            xi[a] = *(const u64*)&s_zki[c][blp * 2 + a];
        }
#pragma unroll
        for (int b = 0; b < 4; b++) {
            wr4[b] = *(const u64*)&s_wr [c][op * 4 + b];
            wi4[b] = *(const u64*)&s_wi [c][op * 4 + b];
            nw4[b] = *(const u64*)&s_nwi[c][op * 4 + b];
        }
#pragma unroll
        for (int a = 0; a < 2; a++)
#pragma unroll
            for (int b = 0; b < 4; b++) {
                fma2(ar[a][b], xr[a], wr4[b]); fma2(ar[a][b], xi[a], nw4[b]);
                fma2(ai[a][b], xi[a], wr4[b]); fma2(ai[a][b], xr[a], wi4[b]);
            }
    }
#pragma unroll
    for (int a = 0; a < 2; a++)
#pragma unroll
        for (int b = 0; b < 4; b++) {
            int blc = (blp * 2 + a) * NC + op * 4 + b;
            float* gb = g_G + (((size_t)blc * NP + p) * 2) * NJ + jp * 2;
            *(float2*)gb        = up2(ar[a][b]);
            *(float2*)(gb + NJ) = up2(ai[a][b]);
        }
}

// ---------------- inverse H-DFT v2: register-blocked, recurrence twiddles ----------------
__global__ __launch_bounds__(256) void invH2() {
    __shared__ __align__(16) float SE[2][33][36];
    __shared__ __align__(16) float SD[2][33][36];
    int blo = blockIdx.x, t = threadIdx.x;
    const float* src = g_G + (size_t)blo * NP * 64;
    for (int f = t; f < 33 * 16; f += 256) {
        int r = f >> 4, c4 = (f & 15) * 4;
        int comp = c4 >> 5, cc = c4 & 31;
        float4 a = *(const float4*)(src + r * 64 + c4);
        float4 e, d;
        if (r == 0) {
            e = a; d = make_float4(0.f, 0.f, 0.f, 0.f);
        } else if (r == 32) {
            e = a;
            if (comp == 0) d = make_float4(-a.x, -a.y, -a.z, -a.w);
            else           d = a;
        } else {
            float4 b = *(const float4*)(src + (64 - r) * 64 + c4);
            e = make_float4(a.x + b.x, a.y + b.y, a.z + b.z, a.w + b.w);
            if (comp == 0) d = make_float4(a.x - b.x, a.y - b.y, a.z - b.z, a.w - b.w);
            else           d = make_float4(b.x - a.x, b.y - a.y, b.z - a.z, b.w - a.w);
        }
        *(float4*)&SE[comp][r][cc] = e;
        *(float4*)&SD[comp ^ 1][r][cc] = d;
    }
    __syncthreads();

    int tx = t & 7, ty = t >> 3;
    int compo = tx >> 2, bf = (tx & 3) * 8;
    const float* pe = &SE[compo][0][bf];
    const float* pd = &SD[compo][0][bf];

    u64 cd[4], sd[4], c1[4], s1[4], ns1[4];
#pragma unroll
    for (int i = 0; i < 4; i++) {
        int h = ty * 4 + i;
        float ss, cc2; sincospif((float)h * (1.0f / 64.0f), &ss, &cc2);
        c1[i] = dup2(cc2); s1[i] = dup2(ss); ns1[i] = dup2(-ss);
        cd[i] = dup2(1.0f); sd[i] = dup2(0.0f);
    }
    u64 acc[4][4];
#pragma unroll
    for (int i = 0; i < 4; i++)
#pragma unroll
        for (int m = 0; m < 4; m++) acc[i][m] = 0ull;

    for (int r = 0; r < 33; r++) {
        ulonglong2 e01 = *(const ulonglong2*)(pe + r * 36);
        ulonglong2 e23 = *(const ulonglong2*)(pe + r * 36 + 4);
        ulonglong2 d01 = *(const ulonglong2*)(pd + r * 36);
        ulonglong2 d23 = *(const ulonglong2*)(pd + r * 36 + 4);
#pragma unroll
        for (int i = 0; i < 4; i++) {
            fma2(acc[i][0], cd[i], e01.x); fma2(acc[i][1], cd[i], e01.y);
            fma2(acc[i][2], cd[i], e23.x); fma2(acc[i][3], cd[i], e23.y);
            fma2(acc[i][0], sd[i], d01.x); fma2(acc[i][1], sd[i], d01.y);
            fma2(acc[i][2], sd[i], d23.x); fma2(acc[i][3], sd[i], d23.y);
            u64 nc = mul2(cd[i], c1[i]); fma2(nc, sd[i], ns1[i]);
            u64 ns = mul2(sd[i], c1[i]); fma2(ns, cd[i], s1[i]);
            cd[i] = nc; sd[i] = ns;
        }
    }
    u64 sc = dup2(1.0f / 128.0f);
#pragma unroll
    for (int i = 0; i < 4; i++) {
        int h = ty * 4 + i;
        float* dst = g_tmp + ((size_t)blo * NH + h) * 64 + compo * 32 + (tx & 3) * 8;
        *(ulonglong2*)dst       = make_ulonglong2(mul2(acc[i][0], sc), mul2(acc[i][1], sc));
        *(ulonglong2*)(dst + 4) = make_ulonglong2(mul2(acc[i][2], sc), mul2(acc[i][3], sc));
    }
}

// ---------------- inverse W c2r, mirror-folded ----------------
// Cc[w'] = Tr . DIc[:,w'],  Cs[w'] = Ti . DIs[:,w']  (w' = 0..127)
// out[w'] = Cc+Cs ; out[256-w'] = Cc-Cs (w'>=1) ; out[128] separate kernel
__global__ __launch_bounds__(256, 2) void gemm_inv(float* __restrict__ out) {
    extern __shared__ __align__(16) float sm[];
    float2* Rr2 = (float2*)sm;               // [32][130]
    float2* Ri2 = Rr2 + 32 * 130;            // [32][130]
    float*  Bc  = (float*)(Ri2 + 32 * 130);  // [32][68]
    float*  Bs  = Bc + 32 * 68;              // [32][68]

    int bx = blockIdx.x;                     // w' block: 0 -> 0..63, 1 -> 64..127
    int by = blockIdx.y;
    int t = threadIdx.x;
    int tx = t & 15, ty = t >> 4;            // tx: 4 w' each; ty: 8 rows each

    // stage A (tmp rows, dup pairs, transposed)
    const float* src = g_tmp + (size_t)by * 128 * 64;
#pragma unroll
    for (int q = 0; q < 8; q++) {
        int f = t + 256 * q;                 // 2048 float4 units: row*16 + fc
        int row = f >> 4, fc = f & 15;
        float4 v = *(const float4*)(src + (size_t)row * 64 + fc * 4);
        float2* dst = (fc < 8) ? Rr2 : Ri2;
        int kb = (fc & 7) * 4;
        dst[(kb + 0) * 130 + row] = make_float2(v.x, v.x);
        dst[(kb + 1) * 130 + row] = make_float2(v.y, v.y);
        dst[(kb + 2) * 130 + row] = make_float2(v.z, v.z);
        dst[(kb + 3) * 130 + row] = make_float2(v.w, v.w);
    }
    // stage B columns for this w' block
#pragma unroll
    for (int q = 0; q < 4; q++) {
        int f = t + 256 * q;                 // 1024 float4 units: arr*512 + k*16 + wl4
        int arr = f >> 9, rem = f & 511;
        int k = rem >> 4, wl4 = (rem & 15) * 4;
        float4 v = *(const float4*)(g_DI + (size_t)(arr * 32 + k) * 256 + bx * 64 + wl4);
        float* dst = arr ? Bs : Bc;
        *(float4*)&dst[k * 68 + wl4] = v;
    }
    __syncthreads();

    u64 Cc[8][2], Cs[8][2];
#pragma unroll
    for (int i = 0; i < 8; i++)
#pragma unroll
        for (int m = 0; m < 2; m++) { Cc[i][m] = 0ull; Cs[i][m] = 0ull; }

#pragma unroll 8
    for (int k = 0; k < 32; k++) {
        ulonglong2 bc = *(const ulonglong2*)&Bc[k * 68 + tx * 4];
        ulonglong2 bs = *(const ulonglong2*)&Bs[k * 68 + tx * 4];
        const ulonglong2* pr = (const ulonglong2*)&Rr2[k * 130 + ty * 8];
        const ulonglong2* pi = (const ulonglong2*)&Ri2[k * 130 + ty * 8];
        ulonglong2 r01 = pr[0], r23 = pr[1], r45 = pr[2], r67 = pr[3];
        ulonglong2 i01 = pi[0], i23 = pi[1], i45 = pi[2], i67 = pi[3];
        u64 aR[8] = {r01.x, r01.y, r23.x, r23.y, r45.x, r45.y, r67.x, r67.y};
        u64 aI[8] = {i01.x, i01.y, i23.x, i23.y, i45.x, i45.y, i67.x, i67.y};
#pragma unroll
        for (int i = 0; i < 8; i++) {
            fma2(Cc[i][0], aR[i], bc.x);
            fma2(Cc[i][1], aR[i], bc.y);
            fma2(Cs[i][0], aI[i], bs.x);
            fma2(Cs[i][1], aI[i], bs.y);
        }
    }
    u64 P1 = dup2(1.0f), N1 = dup2(-1.0f);
#pragma unroll
    for (int i = 0; i < 8; i++) {
        float* ob = out + (size_t)((size_t)by * 128 + ty * 8 + i) * 256;
#pragma unroll
        for (int m = 0; m < 2; m++) {
            int w0 = bx * 64 + tx * 4 + m * 2;
            u64 lo = Cc[i][m]; fma2(lo, P1, Cs[i][m]);
            u64 hi = Cc[i][m]; fma2(hi, N1, Cs[i][m]);
            *(float2*)&ob[w0] = up2(lo);
            float2 hf = up2(hi);
            if (w0 > 0) ob[256 - w0] = hf.x;
            ob[255 - w0] = hf.y;
        }
    }
}

// ---------------- out[:,128] = Tr . coef ----------------
__global__ __launch_bounds__(256) void out128(float* __restrict__ out) {
    int row = blockIdx.x * 256 + threadIdx.x;   // 131072 rows
    const float* tr = g_tmp + (size_t)row * 64;
    const float sc = 2.0f / 256.0f;
    float s = 0.0f;
#pragma unroll
    for (int q = 0; q < 8; q++) {
        float4 v = *(const float4*)(tr + q * 4);
        float x0 = (q == 0) ? 0.5f * v.x : v.x;
        s += (x0 - v.y) + (v.z - v.w);
    }
    out[(size_t)row * 256 + 128] = s * sc;
}

// ---------------- host launcher ----------------
extern "C" void kernel_launch(void* const* d_in, const int* in_sizes, int n_in,
                              void* d_out, int out_size) {
    const float* x   = (const float*)d_in[0];
    const float* k   = (const float*)d_in[1];
    const float* w1r = (const float*)d_in[2];
    const float* w1i = (const float*)d_in[3];
    const float* w2r = (const float*)d_in[4];
    const float* w2i = (const float*)d_in[5];
    float* out = (float*)d_out;
    (void)in_sizes; (void)n_in; (void)out_size;

    void *pT, *pZ;
    cudaGetSymbolAddress(&pT, g_T);
    cudaGetSymbolAddress(&pZ, g_Z);

    const int FWD_SMEM = (16 * 130 * 2 * 2 + 128 * 34 * 2 + 128) * 4;   // 68096 B
    const int INV_SMEM = (32 * 130 * 2 * 2 + 32 * 68 * 2) * 4;          // 83968 B
    cudaFuncSetAttribute(gemm_fwd, cudaFuncAttributeMaxDynamicSharedMemorySize, FWD_SMEM);
    cudaFuncSetAttribute(gemm_inv, cudaFuncAttributeMaxDynamicSharedMemorySize, INV_SMEM);

    init_twiddles<<<64, 256>>>();
    prep_w<<<2048, 256>>>(w1r, w1i, w2r, w2i);

    // forward W-DFT (mirror-folded) over x + k row-blocks
    gemm_fwd<<<NBATT, 128, FWD_SMEM>>>(x, k, NBAT, (float*)pT);

    // forward H-DFT over x + k batches
    fwdH2<<<NBATT, 128>>>((const float*)pT, (float*)pZ);

    // per-mode conv + channel mix
    mix2<<<NP * 16, 128>>>();

    // inverse H-DFT
    invH2<<<NBAT, 256>>>();

    // inverse W c2r (mirror-folded) -> out, plus the w=128 column
    gemm_inv<<<dim3(2, NBAT), 256, INV_SMEM>>>(out);
    out128<<<512, 256>>>(out);
}